// round 14
// baseline (speedup 1.0000x reference)
#include <cuda_runtime.h>

// Problem constants
#define S_LEN   1024
#define DK      64
#define BH      96
#define NTHREADS 256
#define CTX_ELEMS ((size_t)BH * S_LEN * DK)

// ---- dynamic smem layout (words) ----
// s_k [64*68] K tile   (B-frag banks (4n+kk)%32 unique)
// s_v [64*72] V tile   (B-frag banks (8kk+n)%32 unique)
// s_q [64*68] Q tile   (A-frag banks (4g+t)%32 unique)
// s_p [64*68] unnormalized P, tf32 (A-frag banks unique)
#define OFF_K 0
#define OFF_V (64 * 68)
#define OFF_Q (64 * 68 + 64 * 72)
#define OFF_P (2 * 64 * 68 + 64 * 72)
#define SMEM_WORDS (3 * 64 * 68 + 64 * 72)
#define SMEM_BYTES (SMEM_WORDS * 4)          // 70,656 B -> 3 CTAs/SM

__device__ __forceinline__ unsigned smem_u32(const void* p) {
    unsigned a;
    asm("{ .reg .u64 t; cvta.to.shared.u64 t, %1; cvt.u32.u64 %0, t; }"
        : "=r"(a) : "l"(p));
    return a;
}
__device__ __forceinline__ unsigned f2tf(float f) {
    unsigned u;
    asm("cvt.rna.tf32.f32 %0, %1;" : "=r"(u) : "f"(f));
    return u;
}
__device__ __forceinline__ void cp16(unsigned dst, const void* src) {
    asm volatile("cp.async.cg.shared.global [%0], [%1], 16;"
                 :: "r"(dst), "l"(src) : "memory");
}
#define CP_COMMIT() asm volatile("cp.async.commit_group;" ::: "memory")
#define CP_WAIT0()  asm volatile("cp.async.wait_group 0;" ::: "memory")

__device__ __forceinline__ void mma_tf32(float c[4], const unsigned a[4],
                                         unsigned b0, unsigned b1) {
    asm volatile(
        "mma.sync.aligned.m16n8k8.row.col.f32.tf32.tf32.f32 "
        "{%0,%1,%2,%3}, {%4,%5,%6,%7}, {%8,%9}, {%0,%1,%2,%3};\n"
        : "+f"(c[0]), "+f"(c[1]), "+f"(c[2]), "+f"(c[3])
        : "r"(a[0]), "r"(a[1]), "r"(a[2]), "r"(a[3]), "r"(b0), "r"(b1));
}

// Single-pass fused attention:
//   per key tile: QK^T -> mask -> exp -> store UNNORMALIZED attn + stage P
//                 -> PV accumulates unnormalized O  (2 syncs/tile)
//   tail (sync-free): ctx = O * inv;  attn slice RMW: *= inv[row]
__global__ __launch_bounds__(NTHREADS, 3)
void attn_kernel(const float* __restrict__ Q, const float* __restrict__ K,
                 const float* __restrict__ V, const void* __restrict__ maskp,
                 float* __restrict__ ctx_out, float* __restrict__ attn_out)
{
    extern __shared__ __align__(16) unsigned sm[];
    __shared__ float s_rowsum[64];
    __shared__ float s_inv[64];

    unsigned* s_q = sm + OFF_Q;
    unsigned* s_p = sm + OFF_P;

    const int tid  = threadIdx.x;
    const int w    = tid >> 5;
    const int lane = tid & 31;
    const int mr   = w & 3;        // row group: rows mr*16 .. +15
    const int nc   = w >> 2;       // col group: cols nc*32 .. +31
    const int g    = lane >> 2;
    const int t    = lane & 3;
    const int bh    = blockIdx.y;
    const int qbase = blockIdx.x * 64;

    const size_t qkv_base = (size_t)bh * S_LEN * DK;
    const size_t attn_bh  = (size_t)bh * S_LEN * S_LEN;
    const unsigned smb = smem_u32(sm);

    if (tid < 64) s_rowsum[tid] = 0.f;

    // ---- mask dtype probe on first 4KB (word-sized 0/1/1.0f vs packed bytes)
    unsigned other = 0;
    {
        const unsigned* mw = (const unsigned*)maskp;
        #pragma unroll
        for (int i = 0; i < 4; ++i) {
            unsigned x = mw[tid * 4 + i];
            if (x != 0u && x != 1u && x != 0x3F800000u) other = 1;
        }
    }
    const int byte_mode = __syncthreads_or((int)other);

    const unsigned char* mu8  = (const unsigned char*)maskp;
    const int*           mwrd = (const int*)maskp;

    // ---- prologue: cp.async K(0) + stage Q (tf32) --------------------------
    {
        const float* Kp = K + qkv_base;
        #pragma unroll
        for (int i = 0; i < 4; ++i) {
            int f = i * NTHREADS + tid;
            int r = f >> 4, c = (f & 15) * 4;
            cp16(smb + (unsigned)(OFF_K + r * 68 + c) * 4, Kp + r * DK + c);
        }
        CP_COMMIT();
        const float* Qp = Q + qkv_base + (size_t)qbase * DK;
        #pragma unroll
        for (int i = 0; i < 4; ++i) {
            int f = i * NTHREADS + tid;
            int r = f >> 4, c = (f & 15) * 4;
            float4 v = *(const float4*)(Qp + r * DK + c);
            *(uint4*)&s_q[r * 68 + c] =
                make_uint4(f2tf(v.x), f2tf(v.y), f2tf(v.z), f2tf(v.w));
        }
    }

    const int row0c = mr * 16 + g;
    const int grow0 = qbase + row0c;
    float rs0 = 0.f, rs1 = 0.f;

    float oc[4][4];
    #pragma unroll
    for (int j = 0; j < 4; ++j) { oc[j][0]=0.f; oc[j][1]=0.f; oc[j][2]=0.f; oc[j][3]=0.f; }

    // ======================= MAIN LOOP (single pass) =======================
    for (int kt = 0; kt < 16; ++kt) {
        CP_WAIT0();            // my K(kt) chunks landed (prefetched last PV)
        __syncthreads();       // publish K(kt) (+ Q/prologue on kt==0);
                               // also: all warps done with PV(kt-1) -> s_v free
        {                      // issue V(kt) now; overlapped by QK^T + epilogue
            const float* Vp = V + qkv_base + (size_t)(kt * 64) * DK;
            #pragma unroll
            for (int i = 0; i < 4; ++i) {
                int f = i * NTHREADS + tid;
                int r = f >> 4, c = (f & 15) * 4;
                cp16(smb + (unsigned)(OFF_V + r * 72 + c) * 4, Vp + r * DK + c);
            }
            CP_COMMIT();
        }

        // QK^T: A-frags from s_q (tf32), B-frags raw fp32 K + inline RNA cvt
        float sc[4][4];
        #pragma unroll
        for (int j = 0; j < 4; ++j) { sc[j][0]=0.f; sc[j][1]=0.f; sc[j][2]=0.f; sc[j][3]=0.f; }

        #pragma unroll
        for (int ki = 0; ki < 8; ++ki) {
            int kk = ki * 8 + t;
            unsigned a[4];
            a[0] = s_q[row0c * 68 + kk];
            a[1] = s_q[(row0c + 8) * 68 + kk];
            a[2] = s_q[row0c * 68 + kk + 4];
            a[3] = s_q[(row0c + 8) * 68 + kk + 4];
            #pragma unroll
            for (int j = 0; j < 4; ++j) {
                int n = nc * 32 + j * 8 + g;
                unsigned b0 = f2tf(__uint_as_float(sm[OFF_K + n * 68 + kk]));
                unsigned b1 = f2tf(__uint_as_float(sm[OFF_K + n * 68 + kk + 4]));
                mma_tf32(sc[j], a, b0, b1);
            }
        }

        // epilogue: mask, exp, UNNORMALIZED attn store, row sums, P -> s_p
        #pragma unroll
        for (int j = 0; j < 4; ++j) {
            int col_l = nc * 32 + j * 8 + 2 * t;
            size_t off0 = attn_bh + (size_t)grow0 * S_LEN + kt * 64 + col_l;
            size_t off1 = off0 + (size_t)8 * S_LEN;
            unsigned m0, m1, m2, m3;
            if (byte_mode) {
                unsigned short a = __ldcs((const unsigned short*)(mu8 + off0));
                unsigned short b = __ldcs((const unsigned short*)(mu8 + off1));
                m0 = a & 0xFFu; m1 = a >> 8;
                m2 = b & 0xFFu; m3 = b >> 8;
            } else {           // int32 (0/1) and float32 (0.0/1.0): word != 0
                int2 a = __ldcs((const int2*)(mwrd + off0));
                int2 b = __ldcs((const int2*)(mwrd + off1));
                m0 = (unsigned)a.x; m1 = (unsigned)a.y;
                m2 = (unsigned)b.x; m3 = (unsigned)b.y;
            }
            float p0 = m0 ? 0.f : __expf(sc[j][0] * 0.125f);
            float p1 = m1 ? 0.f : __expf(sc[j][1] * 0.125f);
            float p2 = m2 ? 0.f : __expf(sc[j][2] * 0.125f);
            float p3 = m3 ? 0.f : __expf(sc[j][3] * 0.125f);
            rs0 += p0 + p1;
            rs1 += p2 + p3;
            __stcs((float2*)(attn_out + off0), make_float2(p0, p1));
            __stcs((float2*)(attn_out + off1), make_float2(p2, p3));
            *(uint2*)&s_p[row0c * 68 + col_l]       = make_uint2(f2tf(p0), f2tf(p1));
            *(uint2*)&s_p[(row0c + 8) * 68 + col_l] = make_uint2(f2tf(p2), f2tf(p3));
        }

        CP_WAIT0();            // my V(kt) chunks landed (issued before QK^T)
        __syncthreads();       // publish V(kt) + all warps' s_p writes

        // PV: O += P(unnorm) @ V   + prefetch K(kt+1) under the MMA
        if (kt < 15) {
            const float* Kp = K + qkv_base + (size_t)((kt + 1) * 64) * DK;
            #pragma unroll
            for (int i = 0; i < 4; ++i) {
                int f = i * NTHREADS + tid;
                int r = f >> 4, c = (f & 15) * 4;
                cp16(smb + (unsigned)(OFF_K + r * 68 + c) * 4, Kp + r * DK + c);
            }
            CP_COMMIT();
        }
        #pragma unroll
        for (int ki = 0; ki < 8; ++ki) {
            int kk = ki * 8 + t;
            unsigned a[4];
            a[0] = s_p[row0c * 68 + kk];
            a[1] = s_p[(row0c + 8) * 68 + kk];
            a[2] = s_p[row0c * 68 + kk + 4];
            a[3] = s_p[(row0c + 8) * 68 + kk + 4];
            #pragma unroll
            for (int j = 0; j < 4; ++j) {
                int n = nc * 32 + j * 8 + g;
                unsigned b0 = f2tf(__uint_as_float(sm[OFF_V + kk * 72 + n]));
                unsigned b1 = f2tf(__uint_as_float(sm[OFF_V + (kk + 4) * 72 + n]));
                mma_tf32(oc[j], a, b0, b1);
            }
        }
    }

    // ---- row sums -> inv ---------------------------------------------------
    rs0 += __shfl_xor_sync(0xFFFFFFFFu, rs0, 1);
    rs0 += __shfl_xor_sync(0xFFFFFFFFu, rs0, 2);
    rs1 += __shfl_xor_sync(0xFFFFFFFFu, rs1, 1);
    rs1 += __shfl_xor_sync(0xFFFFFFFFu, rs1, 2);
    if (t == 0) {
        atomicAdd(&s_rowsum[row0c], rs0);
        atomicAdd(&s_rowsum[row0c + 8], rs1);
    }
    __syncthreads();           // also publishes all unnormalized attn stores
    if (tid < 64) s_inv[tid] = 1.0f / s_rowsum[tid];
    __syncthreads();

    // ---- context = O * inv -------------------------------------------------
    {
        const float inv0 = s_inv[row0c];
        const float inv1 = s_inv[row0c + 8];
        const size_t cb = qkv_base + (size_t)grow0 * DK;
        #pragma unroll
        for (int j = 0; j < 4; ++j) {
            int dcol = nc * 32 + j * 8 + 2 * t;
            *(float2*)(ctx_out + cb + dcol) =
                make_float2(oc[j][0] * inv0, oc[j][1] * inv0);
            *(float2*)(ctx_out + cb + 8 * DK + dcol) =
                make_float2(oc[j][2] * inv1, oc[j][3] * inv1);
        }
    }

    // ---- sync-free tail: normalize this CTA's attn slice (RMW) -------------
    for (int kt = 0; kt < 16; ++kt) {
        float* Ap = attn_out + attn_bh + (size_t)qbase * S_LEN + kt * 64;
        #pragma unroll
        for (int i = 0; i < 4; ++i) {
            int f = i * NTHREADS + tid;
            int r = f >> 4, c4 = (f & 15) * 4;
            float4 p4 = __ldcs((const float4*)(Ap + (size_t)r * S_LEN + c4));
            float iv = s_inv[r];
            p4.x *= iv; p4.y *= iv; p4.z *= iv; p4.w *= iv;
            __stcs((float4*)(Ap + (size_t)r * S_LEN + c4), p4);
        }
    }
}

extern "C" void kernel_launch(void* const* d_in, const int* in_sizes, int n_in,
                              void* d_out, int out_size) {
    const float* Q = (const float*)d_in[0];
    const float* K = (const float*)d_in[1];
    const float* V = (const float*)d_in[2];
    const void*  M = d_in[3];

    float* ctx  = (float*)d_out;                 // tuple order: (context, attn)
    float* attn = (float*)d_out + CTX_ELEMS;

    cudaFuncSetAttribute(attn_kernel,
                         cudaFuncAttributeMaxDynamicSharedMemorySize, SMEM_BYTES);

    dim3 grid(S_LEN / 64, BH);                   // (16, 96)
    attn_kernel<<<grid, NTHREADS, SMEM_BYTES>>>(Q, K, V, M, ctx, attn);
}

// round 15
// speedup vs baseline: 1.1579x; 1.1579x over previous
#include <cuda_runtime.h>

// Problem constants
#define S_LEN   1024
#define DK      64
#define BH      96
#define NTHREADS 256
#define CTX_ELEMS ((size_t)BH * S_LEN * DK)

// ---- dynamic smem layout (words) ----
// [0, 9216): pass 1: K double-buffer (stride 68, offsets 0/4352)
//            pass 2: V double-buffer (stride 72, offsets 0/4608)
// [9216, 13568): pass 2: normalized P (tf32, stride 68)
// [13568, 17664): pass 2: prefetched attn tile (64x64 f32, stride 64)
#define KW    (64 * 68)          // 4352
#define VW    (64 * 72)          // 4608
#define OFF_P (2 * VW)           // 9216
#define OFF_A (2 * VW + 64 * 68) // 13568
#define SMEM_WORDS (2 * VW + 64 * 68 + 64 * 64)
#define SMEM_BYTES (SMEM_WORDS * 4)   // 70,656 B -> 3 CTAs/SM (212 KB)

__device__ __forceinline__ unsigned smem_u32(const void* p) {
    unsigned a;
    asm("{ .reg .u64 t; cvta.to.shared.u64 t, %1; cvt.u32.u64 %0, t; }"
        : "=r"(a) : "l"(p));
    return a;
}
__device__ __forceinline__ unsigned f2tf(float f) {
    unsigned u;
    asm("cvt.rna.tf32.f32 %0, %1;" : "=r"(u) : "f"(f));
    return u;
}
__device__ __forceinline__ void cp16(unsigned dst, const void* src) {
    asm volatile("cp.async.cg.shared.global [%0], [%1], 16;"
                 :: "r"(dst), "l"(src) : "memory");
}
#define CP_COMMIT() asm volatile("cp.async.commit_group;" ::: "memory")
#define CP_WAIT0()  asm volatile("cp.async.wait_group 0;" ::: "memory")

__device__ __forceinline__ void mma_tf32(float c[4], const unsigned a[4],
                                         unsigned b0, unsigned b1) {
    asm volatile(
        "mma.sync.aligned.m16n8k8.row.col.f32.tf32.tf32.f32 "
        "{%0,%1,%2,%3}, {%4,%5,%6,%7}, {%8,%9}, {%0,%1,%2,%3};\n"
        : "+f"(c[0]), "+f"(c[1]), "+f"(c[2]), "+f"(c[3])
        : "r"(a[0]), "r"(a[1]), "r"(a[2]), "r"(a[3]), "r"(b0), "r"(b1));
}

// Fused masked attention (R12 pipeline):
//   pass 1: S=QK^T/8, p=mask?0:exp(S) -> unnormalized attn (streaming) + rowsums
//           byte-mode mask: 2 full-sector LDG.64 per warp-tile, hoisted pre-MMA,
//           redistributed to c-frag lanes via shfl
//   pass 2: attn tile prefetched via cp.async -> *1/rowsum -> rewrite, P@V MMA
__global__ __launch_bounds__(NTHREADS, 3)
void attn_kernel(const float* __restrict__ Q, const float* __restrict__ K,
                 const float* __restrict__ V, const void* __restrict__ maskp,
                 float* __restrict__ ctx_out, float* __restrict__ attn_out)
{
    extern __shared__ __align__(16) unsigned sm[];
    __shared__ float s_rowsum[64];
    __shared__ float s_inv[64];

    const int tid  = threadIdx.x;
    const int w    = tid >> 5;
    const int lane = tid & 31;
    const int mr   = w & 3;        // row group: rows mr*16 .. +15
    const int nc   = w >> 2;       // col group: cols nc*32 .. +31
    const int g    = lane >> 2;
    const int t    = lane & 3;
    const int bh    = blockIdx.y;
    const int qbase = blockIdx.x * 64;

    const size_t qkv_base = (size_t)bh * S_LEN * DK;
    const size_t attn_bh  = (size_t)bh * S_LEN * S_LEN;
    const unsigned smb = smem_u32(sm);

    if (tid < 64) s_rowsum[tid] = 0.f;

    // ---- mask dtype probe on first 4KB (word-sized 0/1/1.0f vs packed bytes)
    unsigned other = 0;
    {
        const unsigned* mw = (const unsigned*)maskp;
        #pragma unroll
        for (int i = 0; i < 4; ++i) {
            unsigned x = mw[tid * 4 + i];
            if (x != 0u && x != 1u && x != 0x3F800000u) other = 1;
        }
    }
    const int byte_mode = __syncthreads_or((int)other);

    const unsigned char* mu8  = (const unsigned char*)maskp;
    const int*           mwrd = (const int*)maskp;

    // ---- Q A-fragments (RNA tf32) in registers -----------------------------
    unsigned qa[8][4];
    {
        const float* Qp = Q + qkv_base + (size_t)(qbase + mr * 16) * DK;
        #pragma unroll
        for (int ki = 0; ki < 8; ++ki) {
            int c0 = ki * 8 + t;
            qa[ki][0] = f2tf(Qp[g * DK + c0]);
            qa[ki][1] = f2tf(Qp[(g + 8) * DK + c0]);
            qa[ki][2] = f2tf(Qp[g * DK + c0 + 4]);
            qa[ki][3] = f2tf(Qp[(g + 8) * DK + c0 + 4]);
        }
    }

    const int row0c = mr * 16 + g;
    const int grow0 = qbase + row0c;
    float rs0 = 0.f, rs1 = 0.f;

    // ---- prologue: prefetch K tile 0 ---------------------------------------
    {
        const float* Kp = K + qkv_base;
        #pragma unroll
        for (int i = 0; i < 4; ++i) {
            int f = i * NTHREADS + tid;
            int r = f >> 4, c = (f & 15) * 4;
            cp16(smb + (unsigned)(r * 68 + c) * 4, Kp + r * DK + c);
        }
        CP_COMMIT();
    }

    // ======================= PASS 1 ========================================
    for (int kt = 0; kt < 16; ++kt) {
        CP_WAIT0();
        __syncthreads();       // K(kt) staged; all warps past MMA of kt-1
        const unsigned kb = (unsigned)(kt & 1) * KW;
        if (kt < 15) {         // prefetch K(kt+1) into the other buffer
            const float* Kp = K + qkv_base + (size_t)((kt + 1) * 64) * DK;
            const unsigned nb = (unsigned)((kt + 1) & 1) * KW;
            #pragma unroll
            for (int i = 0; i < 4; ++i) {
                int f = i * NTHREADS + tid;
                int r = f >> 4, c = (f & 15) * 4;
                cp16(smb + (nb + (unsigned)(r * 68 + c)) * 4, Kp + r * DK + c);
            }
            CP_COMMIT();
        }

        // byte-mode: issue 2 full-sector LDG.64 mask loads NOW (hidden by MMA)
        // lane (g,t) loads row grow0(+8), cols nc*32 + t*8 .. +7 (8 bytes)
        uint2 mb0 = make_uint2(0u, 0u), mb1 = make_uint2(0u, 0u);
        if (byte_mode) {
            size_t mrow = attn_bh + (size_t)grow0 * S_LEN + kt * 64 + nc * 32 + t * 8;
            mb0 = __ldcs((const uint2*)(mu8 + mrow));
            mb1 = __ldcs((const uint2*)(mu8 + mrow + (size_t)8 * S_LEN));
        }

        // QK^T: A-frags from regs, B-frags raw fp32 K + inline RNA cvt
        float sc[4][4];
        #pragma unroll
        for (int j = 0; j < 4; ++j) { sc[j][0]=0.f; sc[j][1]=0.f; sc[j][2]=0.f; sc[j][3]=0.f; }

        #pragma unroll
        for (int ki = 0; ki < 8; ++ki) {
            int kk = ki * 8 + t;
            #pragma unroll
            for (int j = 0; j < 4; ++j) {
                int n = nc * 32 + j * 8 + g;
                unsigned b0 = f2tf(__uint_as_float(sm[kb + n * 68 + kk]));
                unsigned b1 = f2tf(__uint_as_float(sm[kb + n * 68 + kk + 4]));
                mma_tf32(sc[j], qa[ki], b0, b1);
            }
        }

        // epilogue: mask, exp, unnormalized attn store, row sums
        #pragma unroll
        for (int j = 0; j < 4; ++j) {
            int col = kt * 64 + nc * 32 + j * 8 + 2 * t;
            size_t off0 = attn_bh + (size_t)grow0 * S_LEN + col;
            size_t off1 = off0 + (size_t)8 * S_LEN;
            unsigned m0, m1, m2, m3;
            if (byte_mode) {
                // my bytes live in lane (g*4 + j)'s mb0/mb1 at byte pos 2t,2t+1
                int src = g * 4 + j;
                unsigned w0lo = __shfl_sync(0xFFFFFFFFu, mb0.x, src);
                unsigned w0hi = __shfl_sync(0xFFFFFFFFu, mb0.y, src);
                unsigned w1lo = __shfl_sync(0xFFFFFFFFu, mb1.x, src);
                unsigned w1hi = __shfl_sync(0xFFFFFFFFu, mb1.y, src);
                unsigned pair0 = ((t < 2) ? w0lo : w0hi) >> ((t & 1) * 16);
                unsigned pair1 = ((t < 2) ? w1lo : w1hi) >> ((t & 1) * 16);
                m0 = pair0 & 0xFFu; m1 = (pair0 >> 8) & 0xFFu;
                m2 = pair1 & 0xFFu; m3 = (pair1 >> 8) & 0xFFu;
            } else {           // int32 (0/1) / float32 (0.0/1.0): word != 0
                int2 a = __ldcs((const int2*)(mwrd + off0));
                int2 b = __ldcs((const int2*)(mwrd + off1));
                m0 = (unsigned)a.x; m1 = (unsigned)a.y;
                m2 = (unsigned)b.x; m3 = (unsigned)b.y;
            }
            float p0 = m0 ? 0.f : __expf(sc[j][0] * 0.125f);
            float p1 = m1 ? 0.f : __expf(sc[j][1] * 0.125f);
            float p2 = m2 ? 0.f : __expf(sc[j][2] * 0.125f);
            float p3 = m3 ? 0.f : __expf(sc[j][3] * 0.125f);
            rs0 += p0 + p1;
            rs1 += p2 + p3;
            __stcs((float2*)(attn_out + off0), make_float2(p0, p1));
            __stcs((float2*)(attn_out + off1), make_float2(p2, p3));
        }
    }

    // ---- row-sum reduce ----------------------------------------------------
    rs0 += __shfl_xor_sync(0xFFFFFFFFu, rs0, 1);
    rs0 += __shfl_xor_sync(0xFFFFFFFFu, rs0, 2);
    rs1 += __shfl_xor_sync(0xFFFFFFFFu, rs1, 1);
    rs1 += __shfl_xor_sync(0xFFFFFFFFu, rs1, 2);
    if (t == 0) {
        atomicAdd(&s_rowsum[row0c], rs0);
        atomicAdd(&s_rowsum[row0c + 8], rs1);
    }
    __syncthreads();           // all warps past pass-1 MMAs (K buffers free)

    // prefetch V tile 0 + attn tile 0 (overlaps the inv computation)
    {
        const float* Vp = V + qkv_base;
        const float* Ap = attn_out + attn_bh + (size_t)qbase * S_LEN;
        #pragma unroll
        for (int i = 0; i < 4; ++i) {
            int f = i * NTHREADS + tid;
            int r = f >> 4, c = (f & 15) * 4;
            cp16(smb + (unsigned)(r * 72 + c) * 4, Vp + r * DK + c);
            cp16(smb + (unsigned)(OFF_A + r * 64 + c) * 4, Ap + (size_t)r * S_LEN + c);
        }
        CP_COMMIT();
    }
    if (tid < 64) s_inv[tid] = 1.0f / s_rowsum[tid];
    __syncthreads();

    // ======================= PASS 2 ========================================
    unsigned* s_p = sm + OFF_P;
    float oc[4][4];
    #pragma unroll
    for (int j = 0; j < 4; ++j) { oc[j][0]=0.f; oc[j][1]=0.f; oc[j][2]=0.f; oc[j][3]=0.f; }

    for (int kt = 0; kt < 16; ++kt) {
        CP_WAIT0();
        __syncthreads();       // V(kt)+attn(kt) visible; all past PV of kt-1
        const unsigned vb = (unsigned)(kt & 1) * VW;
        if (kt < 15) {         // V(kt+1) now (other buffer, safe immediately)
            const float* Vp = V + qkv_base + (size_t)((kt + 1) * 64) * DK;
            const unsigned nb = (unsigned)((kt + 1) & 1) * VW;
            #pragma unroll
            for (int i = 0; i < 4; ++i) {
                int f = i * NTHREADS + tid;
                int r = f >> 4, c = (f & 15) * 4;
                cp16(smb + (nb + (unsigned)(r * 72 + c)) * 4, Vp + r * DK + c);
            }
        }

        // normalize from SMEM prefetch, rewrite global, stash tf32 P
        {
            float* Ap = attn_out + attn_bh + (size_t)qbase * S_LEN + kt * 64;
            #pragma unroll
            for (int i = 0; i < 4; ++i) {
                int f = i * NTHREADS + tid;
                int r = f >> 4, c4 = (f & 15) * 4;
                float4 p4 = *(float4*)&sm[OFF_A + r * 64 + c4];
                float iv = s_inv[r];
                p4.x *= iv; p4.y *= iv; p4.z *= iv; p4.w *= iv;
                __stcs((float4*)(Ap + (size_t)r * S_LEN + c4), p4);
                *(uint4*)&s_p[r * 68 + c4] =
                    make_uint4(f2tf(p4.x), f2tf(p4.y), f2tf(p4.z), f2tf(p4.w));
            }
        }
        __syncthreads();       // all P staged; s_attn consumed by everyone

        // prefetch attn(kt+1) into s_attn (now safe) + commit with V(kt+1)
        if (kt < 15) {
            const float* An = attn_out + attn_bh + (size_t)qbase * S_LEN + (kt + 1) * 64;
            #pragma unroll
            for (int i = 0; i < 4; ++i) {
                int f = i * NTHREADS + tid;
                int r = f >> 4, c = (f & 15) * 4;
                cp16(smb + (unsigned)(OFF_A + r * 64 + c) * 4, An + (size_t)r * S_LEN + c);
            }
            CP_COMMIT();
        }

        // PV: A-frags from s_p (tf32), B-frags raw fp32 V + inline RNA cvt
        #pragma unroll
        for (int ki = 0; ki < 8; ++ki) {
            int kk = ki * 8 + t;
            unsigned a[4];
            a[0] = s_p[row0c * 68 + kk];
            a[1] = s_p[(row0c + 8) * 68 + kk];
            a[2] = s_p[row0c * 68 + kk + 4];
            a[3] = s_p[(row0c + 8) * 68 + kk + 4];
            #pragma unroll
            for (int j = 0; j < 4; ++j) {
                int n = nc * 32 + j * 8 + g;
                unsigned b0 = f2tf(__uint_as_float(sm[vb + kk * 72 + n]));
                unsigned b1 = f2tf(__uint_as_float(sm[vb + (kk + 4) * 72 + n]));
                mma_tf32(oc[j], a, b0, b1);
            }
        }
    }

    // ---- write context -----------------------------------------------------
    const size_t cb = qkv_base + (size_t)grow0 * DK;
    #pragma unroll
    for (int j = 0; j < 4; ++j) {
        int dcol = nc * 32 + j * 8 + 2 * t;
        *(float2*)(ctx_out + cb + dcol)          = make_float2(oc[j][0], oc[j][1]);
        *(float2*)(ctx_out + cb + 8 * DK + dcol) = make_float2(oc[j][2], oc[j][3]);
    }
}

extern "C" void kernel_launch(void* const* d_in, const int* in_sizes, int n_in,
                              void* d_out, int out_size) {
    const float* Q = (const float*)d_in[0];
    const float* K = (const float*)d_in[1];
    const float* V = (const float*)d_in[2];
    const void*  M = d_in[3];

    float* ctx  = (float*)d_out;                 // tuple order: (context, attn)
    float* attn = (float*)d_out + CTX_ELEMS;

    cudaFuncSetAttribute(attn_kernel,
                         cudaFuncAttributeMaxDynamicSharedMemorySize, SMEM_BYTES);

    dim3 grid(S_LEN / 64, BH);                   // (16, 96)
    attn_kernel<<<grid, NTHREADS, SMEM_BYTES>>>(Q, K, V, M, ctx, attn);
}

// round 16
// speedup vs baseline: 1.1581x; 1.0001x over previous
#include <cuda_runtime.h>
#include <cuda_fp16.h>

// Problem constants
#define S_LEN   1024
#define DK      64
#define BH      96
#define NTHREADS 256
#define CTX_ELEMS ((size_t)BH * S_LEN * DK)

// Unnormalized softmax numerators, fp16 (pass1 -> pass2). 201 MB.
__device__ __align__(16) __half g_ps[(size_t)BH * S_LEN * S_LEN];

// ---- dynamic smem layout (words) ----
// [0, 9216): pass 1: K double-buffer (stride 68, offsets 0/4352)
//            pass 2: V double-buffer (stride 72, offsets 0/4608)
// [9216, 13568): pass 2: normalized P (tf32, stride 68)
// [13568, 17664): pass 2: fp16 scratch tile double-buffer (64x64 half = 2048 words each)
#define KW     (64 * 68)          // 4352
#define VW     (64 * 72)          // 4608
#define OFF_P  (2 * VW)           // 9216
#define OFF_A0 (2 * VW + 64 * 68) // 13568
#define OFF_A1 (OFF_A0 + 2048)
#define SMEM_WORDS (OFF_A1 + 2048)
#define SMEM_BYTES (SMEM_WORDS * 4)   // 70,656 B -> 3 CTAs/SM

__device__ __forceinline__ unsigned smem_u32(const void* p) {
    unsigned a;
    asm("{ .reg .u64 t; cvta.to.shared.u64 t, %1; cvt.u32.u64 %0, t; }"
        : "=r"(a) : "l"(p));
    return a;
}
__device__ __forceinline__ unsigned f2tf(float f) {
    unsigned u;
    asm("cvt.rna.tf32.f32 %0, %1;" : "=r"(u) : "f"(f));
    return u;
}
__device__ __forceinline__ void cp16(unsigned dst, const void* src) {
    asm volatile("cp.async.cg.shared.global [%0], [%1], 16;"
                 :: "r"(dst), "l"(src) : "memory");
}
#define CP_COMMIT() asm volatile("cp.async.commit_group;" ::: "memory")
#define CP_WAIT0()  asm volatile("cp.async.wait_group 0;" ::: "memory")
#define CP_WAIT1()  asm volatile("cp.async.wait_group 1;" ::: "memory")

__device__ __forceinline__ void stcs32(void* p, unsigned v) {
    asm volatile("st.global.cs.b32 [%0], %1;" :: "l"(p), "r"(v) : "memory");
}
__device__ __forceinline__ unsigned h2u(__half2 h) {
    return *(unsigned*)&h;
}

__device__ __forceinline__ void mma_tf32(float c[4], const unsigned a[4],
                                         unsigned b0, unsigned b1) {
    asm volatile(
        "mma.sync.aligned.m16n8k8.row.col.f32.tf32.tf32.f32 "
        "{%0,%1,%2,%3}, {%4,%5,%6,%7}, {%8,%9}, {%0,%1,%2,%3};\n"
        : "+f"(c[0]), "+f"(c[1]), "+f"(c[2]), "+f"(c[3])
        : "r"(a[0]), "r"(a[1]), "r"(a[2]), "r"(a[3]), "r"(b0), "r"(b1));
}

// Fused masked attention (R15 pipeline, fp16 intermediate):
//   pass 1: S=QK^T/8, p=mask?0:exp(S) -> fp16 scratch (streaming) + rowsums
//   pass 2: scratch tile via depth-2 cp.async -> *1/rowsum -> SINGLE fp32 attn
//           write, P@V MMA
__global__ __launch_bounds__(NTHREADS, 3)
void attn_kernel(const float* __restrict__ Q, const float* __restrict__ K,
                 const float* __restrict__ V, const void* __restrict__ maskp,
                 float* __restrict__ ctx_out, float* __restrict__ attn_out)
{
    extern __shared__ __align__(16) unsigned sm[];
    __shared__ float s_rowsum[64];
    __shared__ float s_inv[64];

    const int tid  = threadIdx.x;
    const int w    = tid >> 5;
    const int lane = tid & 31;
    const int mr   = w & 3;        // row group: rows mr*16 .. +15
    const int nc   = w >> 2;       // col group: cols nc*32 .. +31
    const int g    = lane >> 2;
    const int t    = lane & 3;
    const int bh    = blockIdx.y;
    const int qbase = blockIdx.x * 64;

    const size_t qkv_base = (size_t)bh * S_LEN * DK;
    const size_t attn_bh  = (size_t)bh * S_LEN * S_LEN;
    const unsigned smb = smem_u32(sm);
    __half* gs = (__half*)g_ps;

    if (tid < 64) s_rowsum[tid] = 0.f;

    // ---- mask dtype probe on first 4KB (word-sized 0/1/1.0f vs packed bytes)
    unsigned other = 0;
    {
        const unsigned* mw = (const unsigned*)maskp;
        #pragma unroll
        for (int i = 0; i < 4; ++i) {
            unsigned x = mw[tid * 4 + i];
            if (x != 0u && x != 1u && x != 0x3F800000u) other = 1;
        }
    }
    const int byte_mode = __syncthreads_or((int)other);

    const unsigned char* mu8  = (const unsigned char*)maskp;
    const int*           mwrd = (const int*)maskp;

    // ---- Q A-fragments (RNA tf32) in registers -----------------------------
    unsigned qa[8][4];
    {
        const float* Qp = Q + qkv_base + (size_t)(qbase + mr * 16) * DK;
        #pragma unroll
        for (int ki = 0; ki < 8; ++ki) {
            int c0 = ki * 8 + t;
            qa[ki][0] = f2tf(Qp[g * DK + c0]);
            qa[ki][1] = f2tf(Qp[(g + 8) * DK + c0]);
            qa[ki][2] = f2tf(Qp[g * DK + c0 + 4]);
            qa[ki][3] = f2tf(Qp[(g + 8) * DK + c0 + 4]);
        }
    }

    const int row0c = mr * 16 + g;
    const int grow0 = qbase + row0c;
    float rs0 = 0.f, rs1 = 0.f;

    // ---- prologue: prefetch K tile 0 ---------------------------------------
    {
        const float* Kp = K + qkv_base;
        #pragma unroll
        for (int i = 0; i < 4; ++i) {
            int f = i * NTHREADS + tid;
            int r = f >> 4, c = (f & 15) * 4;
            cp16(smb + (unsigned)(r * 68 + c) * 4, Kp + r * DK + c);
        }
        CP_COMMIT();
    }

    // ======================= PASS 1 ========================================
    for (int kt = 0; kt < 16; ++kt) {
        CP_WAIT0();
        __syncthreads();       // K(kt) staged; all warps past MMA of kt-1
        const unsigned kb = (unsigned)(kt & 1) * KW;
        if (kt < 15) {         // prefetch K(kt+1) into the other buffer
            const float* Kp = K + qkv_base + (size_t)((kt + 1) * 64) * DK;
            const unsigned nb = (unsigned)((kt + 1) & 1) * KW;
            #pragma unroll
            for (int i = 0; i < 4; ++i) {
                int f = i * NTHREADS + tid;
                int r = f >> 4, c = (f & 15) * 4;
                cp16(smb + (nb + (unsigned)(r * 68 + c)) * 4, Kp + r * DK + c);
            }
            CP_COMMIT();
        }

        // byte-mode: 2 full-sector LDG.64 mask loads NOW (hidden by MMA)
        uint2 mb0 = make_uint2(0u, 0u), mb1 = make_uint2(0u, 0u);
        if (byte_mode) {
            size_t mrow = attn_bh + (size_t)grow0 * S_LEN + kt * 64 + nc * 32 + t * 8;
            mb0 = __ldcs((const uint2*)(mu8 + mrow));
            mb1 = __ldcs((const uint2*)(mu8 + mrow + (size_t)8 * S_LEN));
        }

        // QK^T
        float sc[4][4];
        #pragma unroll
        for (int j = 0; j < 4; ++j) { sc[j][0]=0.f; sc[j][1]=0.f; sc[j][2]=0.f; sc[j][3]=0.f; }

        #pragma unroll
        for (int ki = 0; ki < 8; ++ki) {
            int kk = ki * 8 + t;
            #pragma unroll
            for (int j = 0; j < 4; ++j) {
                int n = nc * 32 + j * 8 + g;
                unsigned b0 = f2tf(__uint_as_float(sm[kb + n * 68 + kk]));
                unsigned b1 = f2tf(__uint_as_float(sm[kb + n * 68 + kk + 4]));
                mma_tf32(sc[j], qa[ki], b0, b1);
            }
        }

        // epilogue: mask, exp, fp16 scratch store, row sums
        #pragma unroll
        for (int j = 0; j < 4; ++j) {
            int col = kt * 64 + nc * 32 + j * 8 + 2 * t;
            size_t off0 = attn_bh + (size_t)grow0 * S_LEN + col;
            size_t off1 = off0 + (size_t)8 * S_LEN;
            unsigned m0, m1, m2, m3;
            if (byte_mode) {
                int src = g * 4 + j;
                unsigned w0lo = __shfl_sync(0xFFFFFFFFu, mb0.x, src);
                unsigned w0hi = __shfl_sync(0xFFFFFFFFu, mb0.y, src);
                unsigned w1lo = __shfl_sync(0xFFFFFFFFu, mb1.x, src);
                unsigned w1hi = __shfl_sync(0xFFFFFFFFu, mb1.y, src);
                unsigned pair0 = ((t < 2) ? w0lo : w0hi) >> ((t & 1) * 16);
                unsigned pair1 = ((t < 2) ? w1lo : w1hi) >> ((t & 1) * 16);
                m0 = pair0 & 0xFFu; m1 = (pair0 >> 8) & 0xFFu;
                m2 = pair1 & 0xFFu; m3 = (pair1 >> 8) & 0xFFu;
            } else {
                int2 a = __ldcs((const int2*)(mwrd + off0));
                int2 b = __ldcs((const int2*)(mwrd + off1));
                m0 = (unsigned)a.x; m1 = (unsigned)a.y;
                m2 = (unsigned)b.x; m3 = (unsigned)b.y;
            }
            float p0 = m0 ? 0.f : __expf(sc[j][0] * 0.125f);
            float p1 = m1 ? 0.f : __expf(sc[j][1] * 0.125f);
            float p2 = m2 ? 0.f : __expf(sc[j][2] * 0.125f);
            float p3 = m3 ? 0.f : __expf(sc[j][3] * 0.125f);
            rs0 += p0 + p1;
            rs1 += p2 + p3;
            stcs32(gs + off0, h2u(__floats2half2_rn(p0, p1)));
            stcs32(gs + off1, h2u(__floats2half2_rn(p2, p3)));
        }
    }

    // ---- row-sum reduce ----------------------------------------------------
    rs0 += __shfl_xor_sync(0xFFFFFFFFu, rs0, 1);
    rs0 += __shfl_xor_sync(0xFFFFFFFFu, rs0, 2);
    rs1 += __shfl_xor_sync(0xFFFFFFFFu, rs1, 1);
    rs1 += __shfl_xor_sync(0xFFFFFFFFu, rs1, 2);
    if (t == 0) {
        atomicAdd(&s_rowsum[row0c], rs0);
        atomicAdd(&s_rowsum[row0c + 8], rs1);
    }
    __syncthreads();   // scratch stores + rowsums visible CTA-wide; K bufs free

    // prologue-2: V(0) + scratch(0) in one group; scratch(1) in a second
    {
        const float*  Vp = V + qkv_base;
        const __half* Ap = gs + attn_bh + (size_t)qbase * S_LEN;
        #pragma unroll
        for (int i = 0; i < 4; ++i) {
            int f = i * NTHREADS + tid;
            int r = f >> 4, c = (f & 15) * 4;
            cp16(smb + (unsigned)(r * 72 + c) * 4, Vp + r * DK + c);
        }
        #pragma unroll
        for (int i = 0; i < 2; ++i) {
            int f = i * NTHREADS + tid;
            int r = f >> 3, c8 = (f & 7) * 8;
            cp16(smb + OFF_A0 * 4 + (unsigned)(r * 64 + c8) * 2,
                 Ap + (size_t)r * S_LEN + c8);
        }
        CP_COMMIT();   // G_pro = {V(0), scratch(0)}
        #pragma unroll
        for (int i = 0; i < 2; ++i) {
            int f = i * NTHREADS + tid;
            int r = f >> 3, c8 = (f & 7) * 8;
            cp16(smb + OFF_A1 * 4 + (unsigned)(r * 64 + c8) * 2,
                 Ap + (size_t)r * S_LEN + 64 + c8);
        }
        CP_COMMIT();   // G_pro2 = {scratch(1)}
    }
    if (tid < 64) s_inv[tid] = 1.0f / s_rowsum[tid];
    __syncthreads();

    // ======================= PASS 2 ========================================
    unsigned* s_p = sm + OFF_P;
    float oc[4][4];
    #pragma unroll
    for (int j = 0; j < 4; ++j) { oc[j][0]=0.f; oc[j][1]=0.f; oc[j][2]=0.f; oc[j][3]=0.f; }

    for (int kt = 0; kt < 16; ++kt) {
        CP_WAIT1();            // drains V(kt) + scratch(kt); leaves scratch(kt+1)
        __syncthreads();       // publish; all warps past PV of kt-1
        const unsigned vb = (unsigned)(kt & 1) * VW;
        const unsigned ab = (kt & 1) ? OFF_A1 : OFF_A0;

        if (kt < 15) {         // V(kt+1) -> other buffer
            const float* Vp = V + qkv_base + (size_t)((kt + 1) * 64) * DK;
            const unsigned nb = (unsigned)((kt + 1) & 1) * VW;
            #pragma unroll
            for (int i = 0; i < 4; ++i) {
                int f = i * NTHREADS + tid;
                int r = f >> 4, c = (f & 15) * 4;
                cp16(smb + (nb + (unsigned)(r * 72 + c)) * 4, Vp + r * DK + c);
            }
        }
        CP_COMMIT();           // Ga(kt) = {V(kt+1)}

        // normalize from smem fp16, single fp32 attn write, stash tf32 P
        {
            const __half* ha = (const __half*)(sm + ab);
            float* Ap = attn_out + attn_bh + (size_t)qbase * S_LEN + kt * 64;
            #pragma unroll
            for (int i = 0; i < 4; ++i) {
                int f = i * NTHREADS + tid;
                int r = f >> 4, c4 = (f & 15) * 4;
                const __half2* h2 = (const __half2*)(ha + r * 64 + c4);
                float2 lo = __half22float2(h2[0]);
                float2 hi = __half22float2(h2[1]);
                float iv = s_inv[r];
                float4 p4 = make_float4(lo.x * iv, lo.y * iv, hi.x * iv, hi.y * iv);
                __stcs((float4*)(Ap + (size_t)r * S_LEN + c4), p4);
                *(uint4*)&s_p[r * 68 + c4] =
                    make_uint4(f2tf(p4.x), f2tf(p4.y), f2tf(p4.z), f2tf(p4.w));
            }
        }
        __syncthreads();       // s_p published; s_a[kt&1] fully consumed

        if (kt + 2 < 16) {     // scratch(kt+2) -> the buffer just freed
            const __half* An = gs + attn_bh + (size_t)qbase * S_LEN + (kt + 2) * 64;
            #pragma unroll
            for (int i = 0; i < 2; ++i) {
                int f = i * NTHREADS + tid;
                int r = f >> 3, c8 = (f & 7) * 8;
                cp16(smb + ab * 4 + (unsigned)(r * 64 + c8) * 2,
                     An + (size_t)r * S_LEN + c8);
            }
        }
        CP_COMMIT();           // Gb(kt) = {scratch(kt+2)}

        // PV: A-frags from s_p (tf32), B-frags raw fp32 V + inline RNA cvt
        #pragma unroll
        for (int ki = 0; ki < 8; ++ki) {
            int kk = ki * 8 + t;
            unsigned a[4];
            a[0] = s_p[row0c * 68 + kk];
            a[1] = s_p[(row0c + 8) * 68 + kk];
            a[2] = s_p[row0c * 68 + kk + 4];
            a[3] = s_p[(row0c + 8) * 68 + kk + 4];
            #pragma unroll
            for (int j = 0; j < 4; ++j) {
                int n = nc * 32 + j * 8 + g;
                unsigned b0 = f2tf(__uint_as_float(sm[vb + kk * 72 + n]));
                unsigned b1 = f2tf(__uint_as_float(sm[vb + (kk + 4) * 72 + n]));
                mma_tf32(oc[j], a, b0, b1);
            }
        }
    }

    // ---- write context -----------------------------------------------------
    const size_t cb = qkv_base + (size_t)grow0 * DK;
    #pragma unroll
    for (int j = 0; j < 4; ++j) {
        int dcol = nc * 32 + j * 8 + 2 * t;
        *(float2*)(ctx_out + cb + dcol)          = make_float2(oc[j][0], oc[j][1]);
        *(float2*)(ctx_out + cb + 8 * DK + dcol) = make_float2(oc[j][2], oc[j][3]);
    }
}

extern "C" void kernel_launch(void* const* d_in, const int* in_sizes, int n_in,
                              void* d_out, int out_size) {
    const float* Q = (const float*)d_in[0];
    const float* K = (const float*)d_in[1];
    const float* V = (const float*)d_in[2];
    const void*  M = d_in[3];

    float* ctx  = (float*)d_out;                 // tuple order: (context, attn)
    float* attn = (float*)d_out + CTX_ELEMS;

    cudaFuncSetAttribute(attn_kernel,
                         cudaFuncAttributeMaxDynamicSharedMemorySize, SMEM_BYTES);

    dim3 grid(S_LEN / 64, BH);                   // (16, 96)
    attn_kernel<<<grid, NTHREADS, SMEM_BYTES>>>(Q, K, V, M, ctx, attn);
}